// round 4
// baseline (speedup 1.0000x reference)
#include <cuda_runtime.h>
#include <cuda_bf16.h>
#include <cstdint>

// Attention forward: out = softmax(Q K^T / 0.32) V
// B=4, H=16, S=2048, D=128, fp32 in/out.
//
// Flash-attention with split-precision bf16 emulation of fp32 matmuls:
//   x = x1 + x2, x1 = bf16(x), x2 = bf16(x - x1)   (~17-bit effective mantissa)
//   QK: S = q1k1 + q2k1 + q1k2      (3 bf16 mma passes)
//   PV: O = p1v1 + p1v2 + p2v1      (3 bf16 mma passes)
// Online softmax in log2 domain, fp32 accumulators in mma C regs.
// CTA: 128 query rows (8 warps x 16 rows), loop over 32 key tiles of 64.

#define BM   128
#define BN   64
#define DH   128
#define SEQ  2048
#define NTHREADS 256
#define QS   136   // bf16 elems per Q row (128 + 8 pad -> conflict-free frags)
#define KS   136   // bf16 elems per K/V row
#define PS   72    // bf16 elems per P row (64 + 8 pad)

#define N_SQ (BM*QS)
#define N_SK (BN*KS)
#define N_SP (BM*PS)
#define SMEM_ELEMS (2*N_SQ + 4*N_SK + 2*N_SP)
#define SMEM_BYTES (SMEM_ELEMS * 2)

__device__ __forceinline__ float ex2f(float x) {
    float y;
    asm("ex2.approx.ftz.f32 %0, %1;" : "=f"(y) : "f"(x));
    return y;
}

__device__ __forceinline__ uint32_t lds32(const __nv_bfloat16* p) {
    return *reinterpret_cast<const uint32_t*>(p);
}

__device__ __forceinline__ void mma_bf16(float c[4],
                                         uint32_t a0, uint32_t a1, uint32_t a2, uint32_t a3,
                                         uint32_t b0, uint32_t b1) {
    asm volatile(
        "mma.sync.aligned.m16n8k16.row.col.f32.bf16.bf16.f32 "
        "{%0,%1,%2,%3}, {%4,%5,%6,%7}, {%8,%9}, {%0,%1,%2,%3};\n"
        : "+f"(c[0]), "+f"(c[1]), "+f"(c[2]), "+f"(c[3])
        : "r"(a0), "r"(a1), "r"(a2), "r"(a3), "r"(b0), "r"(b1));
}

__device__ __forceinline__ void ldsm_x4_t(uint32_t& r0, uint32_t& r1,
                                          uint32_t& r2, uint32_t& r3, uint32_t saddr) {
    asm volatile("ldmatrix.sync.aligned.m8n8.x4.trans.shared.b16 {%0,%1,%2,%3}, [%4];"
                 : "=r"(r0), "=r"(r1), "=r"(r2), "=r"(r3) : "r"(saddr));
}

__device__ __forceinline__ void split2(float x, __nv_bfloat16& hi, __nv_bfloat16& lo) {
    hi = __float2bfloat16_rn(x);
    lo = __float2bfloat16_rn(x - __bfloat162float(hi));
}

__global__ void __launch_bounds__(NTHREADS, 1)
attn_fwd_kernel(const float* __restrict__ Q,
                const float* __restrict__ K,
                const float* __restrict__ V,
                float* __restrict__ O) {
    extern __shared__ __nv_bfloat16 smem[];
    __nv_bfloat16* sq1 = smem;               // [BM][QS]
    __nv_bfloat16* sq2 = sq1 + N_SQ;
    __nv_bfloat16* sk1 = sq2 + N_SQ;         // [BN][KS]
    __nv_bfloat16* sk2 = sk1 + N_SK;
    __nv_bfloat16* sv1 = sk2 + N_SK;         // [BN][KS] row-major (key, d)
    __nv_bfloat16* sv2 = sv1 + N_SK;
    __nv_bfloat16* sp1 = sv2 + N_SK;         // [BM][PS]
    __nv_bfloat16* sp2 = sp1 + N_SP;

    const int tid  = threadIdx.x;
    const int wid  = tid >> 5;
    const int lane = tid & 31;
    const int g    = lane >> 2;   // groupID 0..7
    const int t    = lane & 3;    // threadID_in_group 0..3
    const int wr   = wid * 16;    // warp's query-row base

    const int mtile = blockIdx.x;
    const int bh    = blockIdx.y;

    const float* Qg  = Q + ((size_t)bh * SEQ + (size_t)mtile * BM) * DH;
    const float* Kg0 = K + (size_t)bh * SEQ * DH;
    const float* Vg0 = V + (size_t)bh * SEQ * DH;
    float*       Og  = O + ((size_t)bh * SEQ + (size_t)mtile * BM) * DH;

    // fold 1/0.32 and log2(e) into Q (softmax in base-2)
    const float qscale = (1.0f / 0.32f) * 1.4426950408889634f;

    // ---- load Q tile, split into (hi, lo) bf16 ----
    #pragma unroll
    for (int i = tid; i < BM * DH / 4; i += NTHREADS) {
        const int row = i >> 5;       // 32 float4 per row
        const int c4  = i & 31;
        float4 v4 = reinterpret_cast<const float4*>(Qg)[i];
        __nv_bfloat16 h0, h1, h2, h3, l0, l1, l2, l3;
        split2(v4.x * qscale, h0, l0);
        split2(v4.y * qscale, h1, l1);
        split2(v4.z * qscale, h2, l2);
        split2(v4.w * qscale, h3, l3);
        __nv_bfloat162* d1 = reinterpret_cast<__nv_bfloat162*>(sq1 + row * QS + c4 * 4);
        __nv_bfloat162* d2 = reinterpret_cast<__nv_bfloat162*>(sq2 + row * QS + c4 * 4);
        d1[0] = __halves2bfloat162(h0, h1);
        d1[1] = __halves2bfloat162(h2, h3);
        d2[0] = __halves2bfloat162(l0, l1);
        d2[1] = __halves2bfloat162(l2, l3);
    }

    // ---- per-row softmax state (log2 domain) & output accumulators ----
    float m_lo = -1e30f, m_hi = -1e30f;
    float l_lo = 0.0f,   l_hi = 0.0f;
    float o[16][4];
    #pragma unroll
    for (int i = 0; i < 16; i++) {
        o[i][0] = 0.f; o[i][1] = 0.f; o[i][2] = 0.f; o[i][3] = 0.f;
    }

    // LDSM lane offsets for V-fragment loads (trans): matrix idx mi = lane>>3
    const int mi = lane >> 3;
    const int mj = lane & 7;
    const uint32_t sv_lane_elem = (uint32_t)(((mi & 1) * 8 + mj) * KS + (mi >> 1) * 8);
    const uint32_t sbase = (uint32_t)__cvta_generic_to_shared(smem);
    const uint32_t sv1_base = sbase + (uint32_t)(2 * N_SQ + 2 * N_SK) * 2u + sv_lane_elem * 2u;
    const uint32_t sv2_base = sv1_base + (uint32_t)N_SK * 2u;

    for (int kt = 0; kt < SEQ / BN; kt++) {
        __syncthreads();   // prior iter done with sk/sv

        // ---- load K,V tiles, split ----
        const float* Kg = Kg0 + (size_t)kt * BN * DH;
        const float* Vg = Vg0 + (size_t)kt * BN * DH;
        #pragma unroll
        for (int i = tid; i < BN * DH / 4; i += NTHREADS) {
            const int row = i >> 5;
            const int c4  = i & 31;
            float4 a4 = reinterpret_cast<const float4*>(Kg)[i];
            float4 b4 = reinterpret_cast<const float4*>(Vg)[i];
            __nv_bfloat16 h0, h1, h2, h3, l0, l1, l2, l3;
            split2(a4.x, h0, l0); split2(a4.y, h1, l1);
            split2(a4.z, h2, l2); split2(a4.w, h3, l3);
            __nv_bfloat162* d1 = reinterpret_cast<__nv_bfloat162*>(sk1 + row * KS + c4 * 4);
            __nv_bfloat162* d2 = reinterpret_cast<__nv_bfloat162*>(sk2 + row * KS + c4 * 4);
            d1[0] = __halves2bfloat162(h0, h1);
            d1[1] = __halves2bfloat162(h2, h3);
            d2[0] = __halves2bfloat162(l0, l1);
            d2[1] = __halves2bfloat162(l2, l3);
            split2(b4.x, h0, l0); split2(b4.y, h1, l1);
            split2(b4.z, h2, l2); split2(b4.w, h3, l3);
            d1 = reinterpret_cast<__nv_bfloat162*>(sv1 + row * KS + c4 * 4);
            d2 = reinterpret_cast<__nv_bfloat162*>(sv2 + row * KS + c4 * 4);
            d1[0] = __halves2bfloat162(h0, h1);
            d1[1] = __halves2bfloat162(h2, h3);
            d2[0] = __halves2bfloat162(l0, l1);
            d2[1] = __halves2bfloat162(l2, l3);
        }
        __syncthreads();

        // ---- S = Q K^T, split-precision: q1k1 + q2k1 + q1k2 ----
        float s[8][4];
        #pragma unroll
        for (int nt = 0; nt < 8; nt++) {
            s[nt][0] = 0.f; s[nt][1] = 0.f; s[nt][2] = 0.f; s[nt][3] = 0.f;
        }
        #pragma unroll
        for (int kc = 0; kc < 8; kc++) {   // k16 chunks over DH=128
            const int ar0 = (wr + g) * QS;
            const int ar1 = (wr + g + 8) * QS;
            const int ac0 = kc * 16 + 2 * t;
            const int ac1 = ac0 + 8;
            const uint32_t a10 = lds32(sq1 + ar0 + ac0);
            const uint32_t a11 = lds32(sq1 + ar1 + ac0);
            const uint32_t a12 = lds32(sq1 + ar0 + ac1);
            const uint32_t a13 = lds32(sq1 + ar1 + ac1);
            const uint32_t a20 = lds32(sq2 + ar0 + ac0);
            const uint32_t a21 = lds32(sq2 + ar1 + ac0);
            const uint32_t a22 = lds32(sq2 + ar0 + ac1);
            const uint32_t a23 = lds32(sq2 + ar1 + ac1);
            #pragma unroll
            for (int nt = 0; nt < 8; nt++) {
                const int br = (nt * 8 + g) * KS;
                const uint32_t b10 = lds32(sk1 + br + ac0);
                const uint32_t b11 = lds32(sk1 + br + ac1);
                const uint32_t b20 = lds32(sk2 + br + ac0);
                const uint32_t b21 = lds32(sk2 + br + ac1);
                mma_bf16(s[nt], a10, a11, a12, a13, b10, b11);  // q1 k1
                mma_bf16(s[nt], a20, a21, a22, a23, b10, b11);  // q2 k1
                mma_bf16(s[nt], a10, a11, a12, a13, b20, b21);  // q1 k2
            }
        }

        // ---- online softmax (base-2) ----
        float mx_lo = -1e30f, mx_hi = -1e30f;
        #pragma unroll
        for (int nt = 0; nt < 8; nt++) {
            mx_lo = fmaxf(mx_lo, fmaxf(s[nt][0], s[nt][1]));
            mx_hi = fmaxf(mx_hi, fmaxf(s[nt][2], s[nt][3]));
        }
        mx_lo = fmaxf(mx_lo, __shfl_xor_sync(0xffffffffu, mx_lo, 1));
        mx_lo = fmaxf(mx_lo, __shfl_xor_sync(0xffffffffu, mx_lo, 2));
        mx_hi = fmaxf(mx_hi, __shfl_xor_sync(0xffffffffu, mx_hi, 1));
        mx_hi = fmaxf(mx_hi, __shfl_xor_sync(0xffffffffu, mx_hi, 2));

        const float mnew_lo = fmaxf(m_lo, mx_lo);
        const float mnew_hi = fmaxf(m_hi, mx_hi);
        const float corr_lo = ex2f(m_lo - mnew_lo);
        const float corr_hi = ex2f(m_hi - mnew_hi);
        m_lo = mnew_lo;
        m_hi = mnew_hi;

        float sum_lo = 0.f, sum_hi = 0.f;
        #pragma unroll
        for (int nt = 0; nt < 8; nt++) {
            s[nt][0] = ex2f(s[nt][0] - m_lo);
            s[nt][1] = ex2f(s[nt][1] - m_lo);
            s[nt][2] = ex2f(s[nt][2] - m_hi);
            s[nt][3] = ex2f(s[nt][3] - m_hi);
            sum_lo += s[nt][0] + s[nt][1];
            sum_hi += s[nt][2] + s[nt][3];
        }
        sum_lo += __shfl_xor_sync(0xffffffffu, sum_lo, 1);
        sum_lo += __shfl_xor_sync(0xffffffffu, sum_lo, 2);
        sum_hi += __shfl_xor_sync(0xffffffffu, sum_hi, 1);
        sum_hi += __shfl_xor_sync(0xffffffffu, sum_hi, 2);

        l_lo = l_lo * corr_lo + sum_lo;
        l_hi = l_hi * corr_hi + sum_hi;

        #pragma unroll
        for (int nt = 0; nt < 16; nt++) {
            o[nt][0] *= corr_lo; o[nt][1] *= corr_lo;
            o[nt][2] *= corr_hi; o[nt][3] *= corr_hi;
        }

        // ---- stage P to smem as (hi, lo) bf16 (warp-private rows) ----
        #pragma unroll
        for (int nt = 0; nt < 8; nt++) {
            __nv_bfloat16 h0, h1, l0, l1;
            split2(s[nt][0], h0, l0);
            split2(s[nt][1], h1, l1);
            *reinterpret_cast<__nv_bfloat162*>(sp1 + (wr + g) * PS + nt * 8 + 2 * t) =
                __halves2bfloat162(h0, h1);
            *reinterpret_cast<__nv_bfloat162*>(sp2 + (wr + g) * PS + nt * 8 + 2 * t) =
                __halves2bfloat162(l0, l1);
            split2(s[nt][2], h0, l0);
            split2(s[nt][3], h1, l1);
            *reinterpret_cast<__nv_bfloat162*>(sp1 + (wr + g + 8) * PS + nt * 8 + 2 * t) =
                __halves2bfloat162(h0, h1);
            *reinterpret_cast<__nv_bfloat162*>(sp2 + (wr + g + 8) * PS + nt * 8 + 2 * t) =
                __halves2bfloat162(l0, l1);
        }
        __syncwarp();

        // ---- O += P V, split-precision: p1v1 + p1v2 + p2v1 ----
        #pragma unroll
        for (int kc = 0; kc < 4; kc++) {   // k16 chunks over BN=64 keys
            const int ar0 = (wr + g) * PS;
            const int ar1 = (wr + g + 8) * PS;
            const int ac0 = kc * 16 + 2 * t;
            const int ac1 = ac0 + 8;
            const uint32_t p10 = lds32(sp1 + ar0 + ac0);
            const uint32_t p11 = lds32(sp1 + ar1 + ac0);
            const uint32_t p12 = lds32(sp1 + ar0 + ac1);
            const uint32_t p13 = lds32(sp1 + ar1 + ac1);
            const uint32_t p20 = lds32(sp2 + ar0 + ac0);
            const uint32_t p21 = lds32(sp2 + ar1 + ac0);
            const uint32_t p22 = lds32(sp2 + ar0 + ac1);
            const uint32_t p23 = lds32(sp2 + ar1 + ac1);
            #pragma unroll
            for (int ntp = 0; ntp < 8; ntp++) {   // pairs of d8 tiles
                const uint32_t off = (uint32_t)(kc * 16 * KS + ntp * 16) * 2u;
                uint32_t v10, v11, v12, v13, v20, v21, v22, v23;
                ldsm_x4_t(v10, v11, v12, v13, sv1_base + off);
                ldsm_x4_t(v20, v21, v22, v23, sv2_base + off);
                // nt even = 2*ntp (regs r0,r1), nt odd (regs r2,r3)
                mma_bf16(o[2 * ntp],     p10, p11, p12, p13, v10, v11);  // p1 v1
                mma_bf16(o[2 * ntp + 1], p10, p11, p12, p13, v12, v13);
                mma_bf16(o[2 * ntp],     p10, p11, p12, p13, v20, v21);  // p1 v2
                mma_bf16(o[2 * ntp + 1], p10, p11, p12, p13, v22, v23);
                mma_bf16(o[2 * ntp],     p20, p21, p22, p23, v10, v11);  // p2 v1
                mma_bf16(o[2 * ntp + 1], p20, p21, p22, p23, v12, v13);
            }
        }
    }

    // ---- normalize and write out ----
    const float inv_lo = 1.0f / l_lo;
    const float inv_hi = 1.0f / l_hi;
    #pragma unroll
    for (int nt = 0; nt < 16; nt++) {
        const int c = nt * 8 + 2 * t;
        *reinterpret_cast<float2*>(Og + (wr + g)     * DH + c) =
            make_float2(o[nt][0] * inv_lo, o[nt][1] * inv_lo);
        *reinterpret_cast<float2*>(Og + (wr + g + 8) * DH + c) =
            make_float2(o[nt][2] * inv_hi, o[nt][3] * inv_hi);
    }
}

extern "C" void kernel_launch(void* const* d_in, const int* in_sizes, int n_in,
                              void* d_out, int out_size) {
    const float* q = (const float*)d_in[0];
    const float* k = (const float*)d_in[1];
    const float* v = (const float*)d_in[2];
    float* out = (float*)d_out;

    cudaFuncSetAttribute(attn_fwd_kernel,
                         cudaFuncAttributeMaxDynamicSharedMemorySize, SMEM_BYTES);

    dim3 grid(SEQ / BM, 64);
    attn_fwd_kernel<<<grid, NTHREADS, SMEM_BYTES>>>(q, k, v, out);
}

// round 7
// speedup vs baseline: 1.1338x; 1.1338x over previous
#include <cuda_runtime.h>
#include <cuda_fp16.h>
#include <cstdint>

// Attention forward: out = softmax(Q K^T / 0.32) V
// B=4, H=16, S=2048, D=128, fp32 in/out.
//
// Flash-attention, split-precision fp16 emulation of fp32 matmuls:
//   x = x1 + x2, x1 = fp16(x), x2 = fp16(x - x1)   (~21-bit effective mantissa)
//   QK: S = q1k1 + q2k1 + q1k2            (3 fp16 mma passes)
//   PV: O = p~ v1 + p~ v2, p~ = fp16(p)   (2 passes; l summed from p~ so the
//                                          dominant-term rounding cancels in o/l)
// cp.async staged pipeline: V(kt) streams during QK, K(kt+1) during softmax/PV.
// CTA: 128 query rows (8 warps x 16 rows), 32 key tiles of 64.

#define BM   128
#define BN   64
#define DH   128
#define SEQ  2048
#define NT   (SEQ/BN)
#define NTHREADS 256
#define QS   136   // fp16 elems per Q row (128 + 8 pad -> conflict-free frags)
#define KS   136   // fp16 elems per K/V row
#define PS   72    // fp16 elems per P row (64 + 8 pad)

#define N_SQ (BM*QS)
#define N_SK (BN*KS)
#define N_SP (BM*PS)
#define HALF_ELEMS (2*N_SQ + 4*N_SK + N_SP)
#define STAGE_OFF_B (HALF_ELEMS*2)           // byte offset of raw fp32 staging
#define SMEM_BYTES  (STAGE_OFF_B + BN*DH*4)  // 190,464 B

__device__ __forceinline__ float ex2f(float x) {
    float y;
    asm("ex2.approx.ftz.f32 %0, %1;" : "=f"(y) : "f"(x));
    return y;
}

__device__ __forceinline__ uint32_t lds32(const __half* p) {
    return *reinterpret_cast<const uint32_t*>(p);
}

__device__ __forceinline__ void mma_f16(float c[4],
                                        uint32_t a0, uint32_t a1, uint32_t a2, uint32_t a3,
                                        uint32_t b0, uint32_t b1) {
    asm volatile(
        "mma.sync.aligned.m16n8k16.row.col.f32.f16.f16.f32 "
        "{%0,%1,%2,%3}, {%4,%5,%6,%7}, {%8,%9}, {%0,%1,%2,%3};\n"
        : "+f"(c[0]), "+f"(c[1]), "+f"(c[2]), "+f"(c[3])
        : "r"(a0), "r"(a1), "r"(a2), "r"(a3), "r"(b0), "r"(b1));
}

__device__ __forceinline__ void ldsm_x4_t(uint32_t& r0, uint32_t& r1,
                                          uint32_t& r2, uint32_t& r3, uint32_t saddr) {
    asm volatile("ldmatrix.sync.aligned.m8n8.x4.trans.shared.b16 {%0,%1,%2,%3}, [%4];"
                 : "=r"(r0), "=r"(r1), "=r"(r2), "=r"(r3) : "r"(saddr));
}

__device__ __forceinline__ void split2h(float x, __half& hi, __half& lo) {
    hi = __float2half_rn(x);
    lo = __float2half_rn(x - __half2float(hi));
}

__device__ __forceinline__ void cp_async16(uint32_t dst_sa, const void* src) {
    asm volatile("cp.async.cg.shared.global [%0], [%1], 16;\n" :: "r"(dst_sa), "l"(src));
}

__global__ void __launch_bounds__(NTHREADS, 1)
attn_fwd_kernel(const float* __restrict__ Q,
                const float* __restrict__ K,
                const float* __restrict__ V,
                float* __restrict__ O) {
    extern __shared__ __half smem[];
    __half* sq1 = smem;               // [BM][QS]
    __half* sq2 = sq1 + N_SQ;
    __half* sk1 = sq2 + N_SQ;         // [BN][KS]
    __half* sk2 = sk1 + N_SK;
    __half* sv1 = sk2 + N_SK;         // [BN][KS] row-major (key, d)
    __half* sv2 = sv1 + N_SK;
    __half* sp  = sv2 + N_SK;         // [BM][PS]  (single fp16 P)
    float*  stage = reinterpret_cast<float*>(smem + HALF_ELEMS);  // [BN*DH] raw

    const int tid  = threadIdx.x;
    const int wid  = tid >> 5;
    const int lane = tid & 31;
    const int g    = lane >> 2;   // groupID 0..7
    const int t    = lane & 3;    // threadID_in_group 0..3
    const int wr   = wid * 16;    // warp's query-row base

    const int mtile = blockIdx.x;
    const int bh    = blockIdx.y;

    const float* Qg  = Q + ((size_t)bh * SEQ + (size_t)mtile * BM) * DH;
    const float* Kg0 = K + (size_t)bh * SEQ * DH;
    const float* Vg0 = V + (size_t)bh * SEQ * DH;
    float*       Og  = O + ((size_t)bh * SEQ + (size_t)mtile * BM) * DH;

    const uint32_t sbase    = (uint32_t)__cvta_generic_to_shared(smem);
    const uint32_t stage_sa = sbase + STAGE_OFF_B;

    // ---- prologue: start K(0) streaming ----
    {
        const float4* src = reinterpret_cast<const float4*>(Kg0);
        #pragma unroll
        for (int i = tid; i < BN * DH / 4; i += NTHREADS)
            cp_async16(stage_sa + i * 16, src + i);
        asm volatile("cp.async.commit_group;\n");
    }

    // fold 1/0.32 and log2(e) into Q (softmax in base-2)
    const float qscale = (1.0f / 0.32f) * 1.4426950408889634f;

    // ---- load Q tile, split into (hi, lo) fp16 ----
    #pragma unroll
    for (int i = tid; i < BM * DH / 4; i += NTHREADS) {
        const int row = i >> 5;       // 32 float4 per row
        const int c4  = i & 31;
        float4 v4 = reinterpret_cast<const float4*>(Qg)[i];
        __half h0, h1, h2, h3, l0, l1, l2, l3;
        split2h(v4.x * qscale, h0, l0);
        split2h(v4.y * qscale, h1, l1);
        split2h(v4.z * qscale, h2, l2);
        split2h(v4.w * qscale, h3, l3);
        __half2* d1 = reinterpret_cast<__half2*>(sq1 + row * QS + c4 * 4);
        __half2* d2 = reinterpret_cast<__half2*>(sq2 + row * QS + c4 * 4);
        d1[0] = __halves2half2(h0, h1);
        d1[1] = __halves2half2(h2, h3);
        d2[0] = __halves2half2(l0, l1);
        d2[1] = __halves2half2(l2, l3);
    }

    // ---- per-row softmax state (log2 domain) & output accumulators ----
    float m_lo = -1e30f, m_hi = -1e30f;
    float l_lo = 0.0f,   l_hi = 0.0f;
    float o[16][4];
    #pragma unroll
    for (int i = 0; i < 16; i++) {
        o[i][0] = 0.f; o[i][1] = 0.f; o[i][2] = 0.f; o[i][3] = 0.f;
    }

    // LDSM lane base for V-fragment loads (x4.trans)
    const int mi = lane >> 3;
    const int mj = lane & 7;
    const uint32_t sv_lane_elem = (uint32_t)(((mi & 1) * 8 + mj) * KS + (mi >> 1) * 8);
    const uint32_t sv1_base = sbase + (uint32_t)(2 * N_SQ + 2 * N_SK) * 2u + sv_lane_elem * 2u;
    const uint32_t sv2_base = sv1_base + (uint32_t)N_SK * 2u;

    for (int kt = 0; kt < NT; kt++) {
        // ---- K(kt) raw has been streaming; land it, then split to sk ----
        asm volatile("cp.async.wait_group 0;\n" ::: "memory");
        __syncthreads();
        #pragma unroll
        for (int i = tid; i < BN * DH / 4; i += NTHREADS) {
            const int row = i >> 5;
            const int c4  = i & 31;
            float4 a4 = reinterpret_cast<const float4*>(stage)[i];
            __half h0, h1, h2, h3, l0, l1, l2, l3;
            split2h(a4.x, h0, l0); split2h(a4.y, h1, l1);
            split2h(a4.z, h2, l2); split2h(a4.w, h3, l3);
            __half2* d1 = reinterpret_cast<__half2*>(sk1 + row * KS + c4 * 4);
            __half2* d2 = reinterpret_cast<__half2*>(sk2 + row * KS + c4 * 4);
            d1[0] = __halves2half2(h0, h1);
            d1[1] = __halves2half2(h2, h3);
            d2[0] = __halves2half2(l0, l1);
            d2[1] = __halves2half2(l2, l3);
        }
        __syncthreads();

        // ---- start V(kt) streaming into stage ----
        {
            const float4* src = reinterpret_cast<const float4*>(Vg0 + (size_t)kt * BN * DH);
            #pragma unroll
            for (int i = tid; i < BN * DH / 4; i += NTHREADS)
                cp_async16(stage_sa + i * 16, src + i);
            asm volatile("cp.async.commit_group;\n");
        }

        // ---- S = Q K^T, split-precision: q1k1 + q2k1 + q1k2 ----
        float s[8][4];
        #pragma unroll
        for (int nt = 0; nt < 8; nt++) {
            s[nt][0] = 0.f; s[nt][1] = 0.f; s[nt][2] = 0.f; s[nt][3] = 0.f;
        }
        #pragma unroll
        for (int kc = 0; kc < 8; kc++) {   // k16 chunks over DH=128
            const int ar0 = (wr + g) * QS;
            const int ar1 = (wr + g + 8) * QS;
            const int ac0 = kc * 16 + 2 * t;
            const int ac1 = ac0 + 8;
            const uint32_t a10 = lds32(sq1 + ar0 + ac0);
            const uint32_t a11 = lds32(sq1 + ar1 + ac0);
            const uint32_t a12 = lds32(sq1 + ar0 + ac1);
            const uint32_t a13 = lds32(sq1 + ar1 + ac1);
            const uint32_t a20 = lds32(sq2 + ar0 + ac0);
            const uint32_t a21 = lds32(sq2 + ar1 + ac0);
            const uint32_t a22 = lds32(sq2 + ar0 + ac1);
            const uint32_t a23 = lds32(sq2 + ar1 + ac1);
            #pragma unroll
            for (int nt = 0; nt < 8; nt++) {
                const int br = (nt * 8 + g) * KS;
                const uint32_t b10 = lds32(sk1 + br + ac0);
                const uint32_t b11 = lds32(sk1 + br + ac1);
                const uint32_t b20 = lds32(sk2 + br + ac0);
                const uint32_t b21 = lds32(sk2 + br + ac1);
                mma_f16(s[nt], a10, a11, a12, a13, b10, b11);  // q1 k1
                mma_f16(s[nt], a20, a21, a22, a23, b10, b11);  // q2 k1
                mma_f16(s[nt], a10, a11, a12, a13, b20, b21);  // q1 k2
            }
        }

        // ---- online softmax (base-2) ----
        float mx_lo = -1e30f, mx_hi = -1e30f;
        #pragma unroll
        for (int nt = 0; nt < 8; nt++) {
            mx_lo = fmaxf(mx_lo, fmaxf(s[nt][0], s[nt][1]));
            mx_hi = fmaxf(mx_hi, fmaxf(s[nt][2], s[nt][3]));
        }
        mx_lo = fmaxf(mx_lo, __shfl_xor_sync(0xffffffffu, mx_lo, 1));
        mx_lo = fmaxf(mx_lo, __shfl_xor_sync(0xffffffffu, mx_lo, 2));
        mx_hi = fmaxf(mx_hi, __shfl_xor_sync(0xffffffffu, mx_hi, 1));
        mx_hi = fmaxf(mx_hi, __shfl_xor_sync(0xffffffffu, mx_hi, 2));

        const float mnew_lo = fmaxf(m_lo, mx_lo);
        const float mnew_hi = fmaxf(m_hi, mx_hi);
        const float corr_lo = ex2f(m_lo - mnew_lo);
        const float corr_hi = ex2f(m_hi - mnew_hi);
        m_lo = mnew_lo;
        m_hi = mnew_hi;

        // p = ex2(s - m), rounded to fp16; l accumulates the ROUNDED values so
        // P rounding cancels through o/l normalization. Store p~ to sp.
        float sum_lo = 0.f, sum_hi = 0.f;
        #pragma unroll
        for (int nt = 0; nt < 8; nt++) {
            const __half h0 = __float2half_rn(ex2f(s[nt][0] - m_lo));
            const __half h1 = __float2half_rn(ex2f(s[nt][1] - m_lo));
            const __half h2 = __float2half_rn(ex2f(s[nt][2] - m_hi));
            const __half h3 = __float2half_rn(ex2f(s[nt][3] - m_hi));
            sum_lo += __half2float(h0) + __half2float(h1);
            sum_hi += __half2float(h2) + __half2float(h3);
            *reinterpret_cast<__half2*>(sp + (wr + g)     * PS + nt * 8 + 2 * t) =
                __halves2half2(h0, h1);
            *reinterpret_cast<__half2*>(sp + (wr + g + 8) * PS + nt * 8 + 2 * t) =
                __halves2half2(h2, h3);
        }
        sum_lo += __shfl_xor_sync(0xffffffffu, sum_lo, 1);
        sum_lo += __shfl_xor_sync(0xffffffffu, sum_lo, 2);
        sum_hi += __shfl_xor_sync(0xffffffffu, sum_hi, 1);
        sum_hi += __shfl_xor_sync(0xffffffffu, sum_hi, 2);

        l_lo = l_lo * corr_lo + sum_lo;
        l_hi = l_hi * corr_hi + sum_hi;

        #pragma unroll
        for (int nt = 0; nt < 16; nt++) {
            o[nt][0] *= corr_lo; o[nt][1] *= corr_lo;
            o[nt][2] *= corr_hi; o[nt][3] *= corr_hi;
        }
        __syncwarp();   // sp rows are warp-private

        // ---- land V(kt), split to sv, then start K(kt+1) ----
        asm volatile("cp.async.wait_group 0;\n" ::: "memory");
        __syncthreads();
        #pragma unroll
        for (int i = tid; i < BN * DH / 4; i += NTHREADS) {
            const int row = i >> 5;
            const int c4  = i & 31;
            float4 b4 = reinterpret_cast<const float4*>(stage)[i];
            __half h0, h1, h2, h3, l0, l1, l2, l3;
            split2h(b4.x, h0, l0); split2h(b4.y, h1, l1);
            split2h(b4.z, h2, l2); split2h(b4.w, h3, l3);
            __half2* d1 = reinterpret_cast<__half2*>(sv1 + row * KS + c4 * 4);
            __half2* d2 = reinterpret_cast<__half2*>(sv2 + row * KS + c4 * 4);
            d1[0] = __halves2half2(h0, h1);
            d1[1] = __halves2half2(h2, h3);
            d2[0] = __halves2half2(l0, l1);
            d2[1] = __halves2half2(l2, l3);
        }
        __syncthreads();
        if (kt + 1 < NT) {
            const float4* src = reinterpret_cast<const float4*>(Kg0 + (size_t)(kt + 1) * BN * DH);
            #pragma unroll
            for (int i = tid; i < BN * DH / 4; i += NTHREADS)
                cp_async16(stage_sa + i * 16, src + i);
            asm volatile("cp.async.commit_group;\n");
        }

        // ---- O += P~ V, 2 passes: p~ v1 + p~ v2 ----
        #pragma unroll
        for (int kc = 0; kc < 4; kc++) {   // k16 chunks over BN=64 keys
            const int ar0 = (wr + g) * PS;
            const int ar1 = (wr + g + 8) * PS;
            const int ac0 = kc * 16 + 2 * t;
            const int ac1 = ac0 + 8;
            const uint32_t p0 = lds32(sp + ar0 + ac0);
            const uint32_t p1 = lds32(sp + ar1 + ac0);
            const uint32_t p2 = lds32(sp + ar0 + ac1);
            const uint32_t p3 = lds32(sp + ar1 + ac1);
            #pragma unroll
            for (int ntp = 0; ntp < 8; ntp++) {   // pairs of d8 tiles
                const uint32_t off = (uint32_t)(kc * 16 * KS + ntp * 16) * 2u;
                uint32_t v10, v11, v12, v13, v20, v21, v22, v23;
                ldsm_x4_t(v10, v11, v12, v13, sv1_base + off);
                ldsm_x4_t(v20, v21, v22, v23, sv2_base + off);
                mma_f16(o[2 * ntp],     p0, p1, p2, p3, v10, v11);  // p~ v1
                mma_f16(o[2 * ntp + 1], p0, p1, p2, p3, v12, v13);
                mma_f16(o[2 * ntp],     p0, p1, p2, p3, v20, v21);  // p~ v2
                mma_f16(o[2 * ntp + 1], p0, p1, p2, p3, v22, v23);
            }
        }
    }

    // ---- normalize and write out ----
    const float inv_lo = 1.0f / l_lo;
    const float inv_hi = 1.0f / l_hi;
    #pragma unroll
    for (int nt = 0; nt < 16; nt++) {
        const int c = nt * 8 + 2 * t;
        *reinterpret_cast<float2*>(Og + (wr + g)     * DH + c) =
            make_float2(o[nt][0] * inv_lo, o[nt][1] * inv_lo);
        *reinterpret_cast<float2*>(Og + (wr + g + 8) * DH + c) =
            make_float2(o[nt][2] * inv_hi, o[nt][3] * inv_hi);
    }
}

extern "C" void kernel_launch(void* const* d_in, const int* in_sizes, int n_in,
                              void* d_out, int out_size) {
    const float* q = (const float*)d_in[0];
    const float* k = (const float*)d_in[1];
    const float* v = (const float*)d_in[2];
    float* out = (float*)d_out;

    cudaFuncSetAttribute(attn_fwd_kernel,
                         cudaFuncAttributeMaxDynamicSharedMemorySize, SMEM_BYTES);

    dim3 grid(SEQ / BM, 64);
    attn_fwd_kernel<<<grid, NTHREADS, SMEM_BYTES>>>(q, k, v, out);
}

// round 11
// speedup vs baseline: 1.3757x; 1.2133x over previous
#include <cuda_runtime.h>
#include <cuda_fp16.h>
#include <cstdint>

// Attention forward: out = softmax(Q K^T / 0.32) V
// B=4, H=16, S=2048, D=128, fp32 in/out.
//
// Flash-attention, split-precision fp16 emulation:
//   QK: S = q1k1 + q2k1 + q1k2  (3 fp16 mma passes, ~21-bit effective)
//   PV: O = p~ v~               (1 pass; v~ = fp16(v), l summed from fp16 p~
//                                so dominant P-rounding cancels in o/l)
// All mma operand fragments loaded via ldmatrix.x4 (4x fewer LDS issues).
// cp.async staged pipeline: V(kt) streams during QK, K(kt+1) during softmax/PV.
// CTA: 128 query rows (8 warps x 16 rows), 32 key tiles of 64.

#define BM   128
#define BN   64
#define DH   128
#define SEQ  2048
#define NT   (SEQ/BN)
#define NTHREADS 256
#define QS   136   // fp16 elems per Q row (272B stride: ldsm conflict-free)
#define KS   136   // fp16 elems per K/V row
#define PS   72    // fp16 elems per P row (144B stride: ldsm conflict-free)

#define N_SQ (BM*QS)
#define N_SK (BN*KS)
#define N_SP (BM*PS)
// layout: sq1, sq2, sk1, sk2, sv1, sp, stage(fp32)
#define HALF_ELEMS (2*N_SQ + 3*N_SK + N_SP)
#define STAGE_OFF_B (HALF_ELEMS*2)
#define SMEM_BYTES  (STAGE_OFF_B + BN*DH*4)   // 173,056 B

__device__ __forceinline__ float ex2f(float x) {
    float y; asm("ex2.approx.ftz.f32 %0, %1;" : "=f"(y) : "f"(x)); return y;
}
__device__ __forceinline__ void mma_f16(float c[4],
                                        uint32_t a0, uint32_t a1, uint32_t a2, uint32_t a3,
                                        uint32_t b0, uint32_t b1) {
    asm volatile(
        "mma.sync.aligned.m16n8k16.row.col.f32.f16.f16.f32 "
        "{%0,%1,%2,%3}, {%4,%5,%6,%7}, {%8,%9}, {%0,%1,%2,%3};\n"
        : "+f"(c[0]), "+f"(c[1]), "+f"(c[2]), "+f"(c[3])
        : "r"(a0), "r"(a1), "r"(a2), "r"(a3), "r"(b0), "r"(b1));
}
__device__ __forceinline__ void ldsm_x4(uint32_t& r0, uint32_t& r1,
                                        uint32_t& r2, uint32_t& r3, uint32_t saddr) {
    asm volatile("ldmatrix.sync.aligned.m8n8.x4.shared.b16 {%0,%1,%2,%3}, [%4];"
                 : "=r"(r0), "=r"(r1), "=r"(r2), "=r"(r3) : "r"(saddr));
}
__device__ __forceinline__ void ldsm_x4_t(uint32_t& r0, uint32_t& r1,
                                          uint32_t& r2, uint32_t& r3, uint32_t saddr) {
    asm volatile("ldmatrix.sync.aligned.m8n8.x4.trans.shared.b16 {%0,%1,%2,%3}, [%4];"
                 : "=r"(r0), "=r"(r1), "=r"(r2), "=r"(r3) : "r"(saddr));
}
__device__ __forceinline__ void split2h(float x, __half& hi, __half& lo) {
    hi = __float2half_rn(x);
    lo = __float2half_rn(x - __half2float(hi));
}
__device__ __forceinline__ void cp_async16(uint32_t dst_sa, const void* src) {
    asm volatile("cp.async.cg.shared.global [%0], [%1], 16;\n" :: "r"(dst_sa), "l"(src));
}

__global__ void __launch_bounds__(NTHREADS, 1)
attn_fwd_kernel(const float* __restrict__ Q,
                const float* __restrict__ K,
                const float* __restrict__ V,
                float* __restrict__ O) {
    extern __shared__ __half smem[];
    __half* sq1 = smem;               // [BM][QS]
    __half* sq2 = sq1 + N_SQ;
    __half* sk1 = sq2 + N_SQ;         // [BN][KS]
    __half* sk2 = sk1 + N_SK;
    __half* sv1 = sk2 + N_SK;         // [BN][KS] row-major (key, d)
    __half* sp  = sv1 + N_SK;         // [BM][PS]
    float*  stage = reinterpret_cast<float*>(smem + HALF_ELEMS);  // [BN*DH] raw

    const int tid  = threadIdx.x;
    const int wid  = tid >> 5;
    const int lane = tid & 31;
    const int g    = lane >> 2;
    const int t    = lane & 3;
    const int wr   = wid * 16;

    const int mtile = blockIdx.x;
    const int bh    = blockIdx.y;

    const float* Qg  = Q + ((size_t)bh * SEQ + (size_t)mtile * BM) * DH;
    const float* Kg0 = K + (size_t)bh * SEQ * DH;
    const float* Vg0 = V + (size_t)bh * SEQ * DH;
    float*       Og  = O + ((size_t)bh * SEQ + (size_t)mtile * BM) * DH;

    const uint32_t sbase    = (uint32_t)__cvta_generic_to_shared(smem);
    const uint32_t stage_sa = sbase + STAGE_OFF_B;

    // ---- prologue: start K(0) streaming ----
    {
        const float4* src = reinterpret_cast<const float4*>(Kg0);
        #pragma unroll
        for (int i = tid; i < BN * DH / 4; i += NTHREADS)
            cp_async16(stage_sa + i * 16, src + i);
        asm volatile("cp.async.commit_group;\n");
    }

    const float qscale = (1.0f / 0.32f) * 1.4426950408889634f;

    // ---- load Q tile, split into (hi, lo) fp16 ----
    #pragma unroll
    for (int i = tid; i < BM * DH / 4; i += NTHREADS) {
        const int row = i >> 5;
        const int c4  = i & 31;
        float4 v4 = reinterpret_cast<const float4*>(Qg)[i];
        __half h0, h1, h2, h3, l0, l1, l2, l3;
        split2h(v4.x * qscale, h0, l0);
        split2h(v4.y * qscale, h1, l1);
        split2h(v4.z * qscale, h2, l2);
        split2h(v4.w * qscale, h3, l3);
        __half2* d1 = reinterpret_cast<__half2*>(sq1 + row * QS + c4 * 4);
        __half2* d2 = reinterpret_cast<__half2*>(sq2 + row * QS + c4 * 4);
        d1[0] = __halves2half2(h0, h1);
        d1[1] = __halves2half2(h2, h3);
        d2[0] = __halves2half2(l0, l1);
        d2[1] = __halves2half2(l2, l3);
    }

    float m_lo = -1e30f, m_hi = -1e30f;
    float l_lo = 0.0f,   l_hi = 0.0f;
    float o[16][4];
    #pragma unroll
    for (int i = 0; i < 16; i++) { o[i][0]=0.f; o[i][1]=0.f; o[i][2]=0.f; o[i][3]=0.f; }

    // ---- ldmatrix lane bases ----
    // A-frag (non-trans, row-major [m][k]): matrices (m0-7,k0-7),(m8-15,k0-7),
    // (m0-7,k8-15),(m8-15,k8-15) -> a0..a3.
    const uint32_t a_row = (uint32_t)(wr + (lane & 7) + ((lane >> 3) & 1) * 8);
    const uint32_t a_c8  = (uint32_t)((lane >> 4) * 8);
    const uint32_t sq1_ld = sbase + (a_row * QS + a_c8) * 2u;
    const uint32_t sq2_ld = sq1_ld + (uint32_t)N_SQ * 2u;
    // B-frag (non-trans, row-major [n][k]): matrices (n0-7,k0),(n0-7,k8),
    // (n8-15,k0),(n8-15,k8) -> r0,r1 = b0,b1 (nt even); r2,r3 = (nt odd).
    const uint32_t b_row = (uint32_t)((lane & 7) + ((lane >> 4) << 3));
    const uint32_t b_c8  = (uint32_t)(((lane >> 3) & 1) * 8);
    const uint32_t sk1_ld = sbase + (uint32_t)(2 * N_SQ) * 2u + (b_row * KS + b_c8) * 2u;
    const uint32_t sk2_ld = sk1_ld + (uint32_t)N_SK * 2u;
    // P-frag (A-style on sp, stride PS)
    const uint32_t sp_ld = sbase + (uint32_t)(2 * N_SQ + 3 * N_SK) * 2u
                         + (a_row * PS + a_c8) * 2u;
    // V-frag (trans ldsm on sv1)
    const int mi = lane >> 3, mj = lane & 7;
    const uint32_t sv_lane_elem = (uint32_t)(((mi & 1) * 8 + mj) * KS + (mi >> 1) * 8);
    const uint32_t sv1_base = sbase + (uint32_t)(2 * N_SQ + 2 * N_SK) * 2u + sv_lane_elem * 2u;

    for (int kt = 0; kt < NT; kt++) {
        // ---- K(kt) raw streamed; land it, split to sk ----
        asm volatile("cp.async.wait_group 0;\n" ::: "memory");
        __syncthreads();
        #pragma unroll
        for (int i = tid; i < BN * DH / 4; i += NTHREADS) {
            const int row = i >> 5;
            const int c4  = i & 31;
            float4 a4 = reinterpret_cast<const float4*>(stage)[i];
            __half h0, h1, h2, h3, l0, l1, l2, l3;
            split2h(a4.x, h0, l0); split2h(a4.y, h1, l1);
            split2h(a4.z, h2, l2); split2h(a4.w, h3, l3);
            __half2* d1 = reinterpret_cast<__half2*>(sk1 + row * KS + c4 * 4);
            __half2* d2 = reinterpret_cast<__half2*>(sk2 + row * KS + c4 * 4);
            d1[0] = __halves2half2(h0, h1);
            d1[1] = __halves2half2(h2, h3);
            d2[0] = __halves2half2(l0, l1);
            d2[1] = __halves2half2(l2, l3);
        }
        __syncthreads();

        // ---- start V(kt) streaming ----
        {
            const float4* src = reinterpret_cast<const float4*>(Vg0 + (size_t)kt * BN * DH);
            #pragma unroll
            for (int i = tid; i < BN * DH / 4; i += NTHREADS)
                cp_async16(stage_sa + i * 16, src + i);
            asm volatile("cp.async.commit_group;\n");
        }

        // ---- S = Q K^T: q1k1 + q2k1 + q1k2, fragments via ldmatrix ----
        float s[8][4];
        #pragma unroll
        for (int nt = 0; nt < 8; nt++) {
            s[nt][0]=0.f; s[nt][1]=0.f; s[nt][2]=0.f; s[nt][3]=0.f;
        }
        #pragma unroll
        for (int kc = 0; kc < 8; kc++) {
            uint32_t a1[4], a2[4];
            ldsm_x4(a1[0], a1[1], a1[2], a1[3], sq1_ld + kc * 32u);
            ldsm_x4(a2[0], a2[1], a2[2], a2[3], sq2_ld + kc * 32u);
            #pragma unroll
            for (int pr = 0; pr < 4; pr++) {   // nt pairs: rows 16*pr..16*pr+15 of K
                const uint32_t boff = (uint32_t)(pr * 16 * KS + kc * 16) * 2u;
                uint32_t b1[4], b2[4];
                ldsm_x4(b1[0], b1[1], b1[2], b1[3], sk1_ld + boff);
                ldsm_x4(b2[0], b2[1], b2[2], b2[3], sk2_ld + boff);
                mma_f16(s[2*pr],   a1[0],a1[1],a1[2],a1[3], b1[0], b1[1]);  // q1k1
                mma_f16(s[2*pr+1], a1[0],a1[1],a1[2],a1[3], b1[2], b1[3]);
                mma_f16(s[2*pr],   a2[0],a2[1],a2[2],a2[3], b1[0], b1[1]);  // q2k1
                mma_f16(s[2*pr+1], a2[0],a2[1],a2[2],a2[3], b1[2], b1[3]);
                mma_f16(s[2*pr],   a1[0],a1[1],a1[2],a1[3], b2[0], b2[1]);  // q1k2
                mma_f16(s[2*pr+1], a1[0],a1[1],a1[2],a1[3], b2[2], b2[3]);
            }
        }

        // ---- online softmax (base-2) ----
        float mx_lo = -1e30f, mx_hi = -1e30f;
        #pragma unroll
        for (int nt = 0; nt < 8; nt++) {
            mx_lo = fmaxf(mx_lo, fmaxf(s[nt][0], s[nt][1]));
            mx_hi = fmaxf(mx_hi, fmaxf(s[nt][2], s[nt][3]));
        }
        mx_lo = fmaxf(mx_lo, __shfl_xor_sync(0xffffffffu, mx_lo, 1));
        mx_lo = fmaxf(mx_lo, __shfl_xor_sync(0xffffffffu, mx_lo, 2));
        mx_hi = fmaxf(mx_hi, __shfl_xor_sync(0xffffffffu, mx_hi, 1));
        mx_hi = fmaxf(mx_hi, __shfl_xor_sync(0xffffffffu, mx_hi, 2));

        const float mnew_lo = fmaxf(m_lo, mx_lo);
        const float mnew_hi = fmaxf(m_hi, mx_hi);
        const float corr_lo = ex2f(m_lo - mnew_lo);
        const float corr_hi = ex2f(m_hi - mnew_hi);
        m_lo = mnew_lo;
        m_hi = mnew_hi;

        float sum_lo = 0.f, sum_hi = 0.f;
        #pragma unroll
        for (int nt = 0; nt < 8; nt++) {
            const __half h0 = __float2half_rn(ex2f(s[nt][0] - m_lo));
            const __half h1 = __float2half_rn(ex2f(s[nt][1] - m_lo));
            const __half h2 = __float2half_rn(ex2f(s[nt][2] - m_hi));
            const __half h3 = __float2half_rn(ex2f(s[nt][3] - m_hi));
            sum_lo += __half2float(h0) + __half2float(h1);
            sum_hi += __half2float(h2) + __half2float(h3);
            *reinterpret_cast<__half2*>(sp + (wr + g)     * PS + nt * 8 + 2 * t) =
                __halves2half2(h0, h1);
            *reinterpret_cast<__half2*>(sp + (wr + g + 8) * PS + nt * 8 + 2 * t) =
                __halves2half2(h2, h3);
        }
        sum_lo += __shfl_xor_sync(0xffffffffu, sum_lo, 1);
        sum_lo += __shfl_xor_sync(0xffffffffu, sum_lo, 2);
        sum_hi += __shfl_xor_sync(0xffffffffu, sum_hi, 1);
        sum_hi += __shfl_xor_sync(0xffffffffu, sum_hi, 2);

        l_lo = l_lo * corr_lo + sum_lo;
        l_hi = l_hi * corr_hi + sum_hi;

        #pragma unroll
        for (int nt = 0; nt < 16; nt++) {
            o[nt][0] *= corr_lo; o[nt][1] *= corr_lo;
            o[nt][2] *= corr_hi; o[nt][3] *= corr_hi;
        }
        __syncwarp();   // sp rows are warp-private

        // ---- land V(kt), convert to fp16 (hi only), then start K(kt+1) ----
        asm volatile("cp.async.wait_group 0;\n" ::: "memory");
        __syncthreads();
        #pragma unroll
        for (int i = tid; i < BN * DH / 4; i += NTHREADS) {
            const int row = i >> 5;
            const int c4  = i & 31;
            float4 b4 = reinterpret_cast<const float4*>(stage)[i];
            __half2* d1 = reinterpret_cast<__half2*>(sv1 + row * KS + c4 * 4);
            d1[0] = __halves2half2(__float2half_rn(b4.x), __float2half_rn(b4.y));
            d1[1] = __halves2half2(__float2half_rn(b4.z), __float2half_rn(b4.w));
        }
        __syncthreads();
        if (kt + 1 < NT) {
            const float4* src = reinterpret_cast<const float4*>(Kg0 + (size_t)(kt + 1) * BN * DH);
            #pragma unroll
            for (int i = tid; i < BN * DH / 4; i += NTHREADS)
                cp_async16(stage_sa + i * 16, src + i);
            asm volatile("cp.async.commit_group;\n");
        }

        // ---- O += P~ V~ (single pass), fragments via ldmatrix ----
        #pragma unroll
        for (int kc = 0; kc < 4; kc++) {
            uint32_t p[4];
            ldsm_x4(p[0], p[1], p[2], p[3], sp_ld + kc * 32u);
            #pragma unroll
            for (int ntp = 0; ntp < 8; ntp++) {
                const uint32_t off = (uint32_t)(kc * 16 * KS + ntp * 16) * 2u;
                uint32_t v0, v1, v2, v3;
                ldsm_x4_t(v0, v1, v2, v3, sv1_base + off);
                mma_f16(o[2*ntp],   p[0], p[1], p[2], p[3], v0, v1);
                mma_f16(o[2*ntp+1], p[0], p[1], p[2], p[3], v2, v3);
            }
        }
    }

    // ---- normalize and write out ----
    const float inv_lo = 1.0f / l_lo;
    const float inv_hi = 1.0f / l_hi;
    #pragma unroll
    for (int nt = 0; nt < 16; nt++) {
        const int c = nt * 8 + 2 * t;
        *reinterpret_cast<float2*>(Og + (wr + g)     * DH + c) =
            make_float2(o[nt][0] * inv_lo, o[nt][1] * inv_lo);
        *reinterpret_cast<float2*>(Og + (wr + g + 8) * DH + c) =
            make_float2(o[nt][2] * inv_hi, o[nt][3] * inv_hi);
    }
}

extern "C" void kernel_launch(void* const* d_in, const int* in_sizes, int n_in,
                              void* d_out, int out_size) {
    const float* q = (const float*)d_in[0];
    const float* k = (const float*)d_in[1];
    const float* v = (const float*)d_in[2];
    float* out = (float*)d_out;

    cudaFuncSetAttribute(attn_fwd_kernel,
                         cudaFuncAttributeMaxDynamicSharedMemorySize, SMEM_BYTES);

    dim3 grid(SEQ / BM, 64);
    attn_fwd_kernel<<<grid, NTHREADS, SMEM_BYTES>>>(q, k, v, out);
}

// round 12
// speedup vs baseline: 1.4275x; 1.0377x over previous
#include <cuda_runtime.h>
#include <cuda_fp16.h>
#include <cstdint>

// Attention forward: out = softmax(Q K^T / 0.32) V
// B=4, H=16, S=2048, D=128, fp32 in/out.
//
// Two kernels:
//  1) split_kv: K -> (khi,klo) fp16, V -> vhi fp16, once into __device__ globals
//     (removes the 16x-redundant per-CTA split work + crossbar traffic).
//  2) attn_fwd: flash attention, QK = q1k1 + q2k1 + q1k2 (split fp16, ~21-bit),
//     PV = p~ v~ (single pass; l summed from fp16 p~ so rounding cancels in o/l).
//     K/V operands cp.async'd DIRECTLY into double-buffered ldsm-layout smem.

#define BM   128
#define BN   64
#define DH   128
#define SEQ  2048
#define NT   (SEQ/BN)
#define NTHREADS 256
#define QS   136
#define KS   136
#define PS   72

#define N_SQ (BM*QS)        // 17408
#define N_SK (BN*KS)        // 8704
#define N_SP (BM*PS)        // 9216
#define BUF_ELEMS (3*N_SK)  // sk1, sk2, sv per buffer
#define SQ2_E  N_SQ
#define BUF0_E (2*N_SQ)
#define SP_E   (BUF0_E + 2*BUF_ELEMS)
#define SMEM_BYTES ((SP_E + N_SP) * 2)   // 192,512 B

#define KVELEMS (64LL*2048*128)
__device__ __half g_khi[KVELEMS];
__device__ __half g_klo[KVELEMS];
__device__ __half g_vhi[KVELEMS];

__device__ __forceinline__ float ex2f(float x) {
    float y; asm("ex2.approx.ftz.f32 %0, %1;" : "=f"(y) : "f"(x)); return y;
}
__device__ __forceinline__ void mma_f16(float c[4],
                                        uint32_t a0, uint32_t a1, uint32_t a2, uint32_t a3,
                                        uint32_t b0, uint32_t b1) {
    asm volatile(
        "mma.sync.aligned.m16n8k16.row.col.f32.f16.f16.f32 "
        "{%0,%1,%2,%3}, {%4,%5,%6,%7}, {%8,%9}, {%0,%1,%2,%3};\n"
        : "+f"(c[0]), "+f"(c[1]), "+f"(c[2]), "+f"(c[3])
        : "r"(a0), "r"(a1), "r"(a2), "r"(a3), "r"(b0), "r"(b1));
}
__device__ __forceinline__ void ldsm_x4(uint32_t& r0, uint32_t& r1,
                                        uint32_t& r2, uint32_t& r3, uint32_t saddr) {
    asm volatile("ldmatrix.sync.aligned.m8n8.x4.shared.b16 {%0,%1,%2,%3}, [%4];"
                 : "=r"(r0), "=r"(r1), "=r"(r2), "=r"(r3) : "r"(saddr));
}
__device__ __forceinline__ void ldsm_x4_t(uint32_t& r0, uint32_t& r1,
                                          uint32_t& r2, uint32_t& r3, uint32_t saddr) {
    asm volatile("ldmatrix.sync.aligned.m8n8.x4.trans.shared.b16 {%0,%1,%2,%3}, [%4];"
                 : "=r"(r0), "=r"(r1), "=r"(r2), "=r"(r3) : "r"(saddr));
}
__device__ __forceinline__ void split2h(float x, __half& hi, __half& lo) {
    hi = __float2half_rn(x);
    lo = __float2half_rn(x - __half2float(hi));
}
__device__ __forceinline__ void cp_async16(uint32_t dst_sa, const void* src) {
    asm volatile("cp.async.cg.shared.global [%0], [%1], 16;\n" :: "r"(dst_sa), "l"(src));
}

// ---- pre-pass: split K into hi/lo fp16, V into hi fp16 ----
__global__ void __launch_bounds__(256) split_kv_kernel(const float* __restrict__ K,
                                                       const float* __restrict__ V) {
    const size_t i = (size_t)blockIdx.x * 256 + threadIdx.x;   // float4 index
    float4 k4 = reinterpret_cast<const float4*>(K)[i];
    __half h0, h1, h2, h3, l0, l1, l2, l3;
    split2h(k4.x, h0, l0); split2h(k4.y, h1, l1);
    split2h(k4.z, h2, l2); split2h(k4.w, h3, l3);
    reinterpret_cast<__half2*>(g_khi)[2*i]   = __halves2half2(h0, h1);
    reinterpret_cast<__half2*>(g_khi)[2*i+1] = __halves2half2(h2, h3);
    reinterpret_cast<__half2*>(g_klo)[2*i]   = __halves2half2(l0, l1);
    reinterpret_cast<__half2*>(g_klo)[2*i+1] = __halves2half2(l2, l3);
    float4 v4 = reinterpret_cast<const float4*>(V)[i];
    reinterpret_cast<__half2*>(g_vhi)[2*i]   =
        __halves2half2(__float2half_rn(v4.x), __float2half_rn(v4.y));
    reinterpret_cast<__half2*>(g_vhi)[2*i+1] =
        __halves2half2(__float2half_rn(v4.z), __float2half_rn(v4.w));
}

// issue cp.async for one K/V tile into buffer b (1024 16B-chunks each of khi/klo/vhi)
__device__ __forceinline__ void issue_kv(int tid, uint32_t buf_sa,
                                         const __half* khsrc, const __half* klsrc,
                                         const __half* vhsrc) {
    #pragma unroll
    for (int j = 0; j < 4; j++) {
        const int i = tid + j * NTHREADS;           // chunk index 0..1023
        const uint32_t dst = (uint32_t)((i >> 4) * (KS * 2) + (i & 15) * 16);
        cp_async16(buf_sa + dst,                       khsrc + (size_t)i * 8);
        cp_async16(buf_sa + N_SK * 2 + dst,            klsrc + (size_t)i * 8);
        cp_async16(buf_sa + 2 * N_SK * 2 + dst,        vhsrc + (size_t)i * 8);
    }
    asm volatile("cp.async.commit_group;\n");
}

__global__ void __launch_bounds__(NTHREADS, 1)
attn_fwd_kernel(const float* __restrict__ Q,
                float* __restrict__ O) {
    extern __shared__ __half smem[];
    __half* sq1 = smem;
    __half* sq2 = sq1 + SQ2_E;
    __half* sp  = smem + SP_E;

    const int tid  = threadIdx.x;
    const int wid  = tid >> 5;
    const int lane = tid & 31;
    const int g    = lane >> 2;
    const int t    = lane & 3;
    const int wr   = wid * 16;

    const int mtile = blockIdx.x;
    const int bh    = blockIdx.y;

    const float*  Qg  = Q + ((size_t)bh * SEQ + (size_t)mtile * BM) * DH;
    const __half* Kh0 = g_khi + (size_t)bh * SEQ * DH;
    const __half* Kl0 = g_klo + (size_t)bh * SEQ * DH;
    const __half* Vh0 = g_vhi + (size_t)bh * SEQ * DH;
    float*        Og  = O + ((size_t)bh * SEQ + (size_t)mtile * BM) * DH;

    const uint32_t sbase = (uint32_t)__cvta_generic_to_shared(smem);
    const uint32_t buf_sa0 = sbase + BUF0_E * 2;
    const uint32_t buf_sa1 = buf_sa0 + BUF_ELEMS * 2;

    // ---- prologue: issue tiles 0 and 1 ----
    issue_kv(tid, buf_sa0, Kh0, Kl0, Vh0);
    issue_kv(tid, buf_sa1, Kh0 + (size_t)BN * DH, Kl0 + (size_t)BN * DH,
             Vh0 + (size_t)BN * DH);

    const float qscale = (1.0f / 0.32f) * 1.4426950408889634f;

    // ---- load Q tile, split into (hi, lo) fp16 ----
    #pragma unroll
    for (int i = tid; i < BM * DH / 4; i += NTHREADS) {
        const int row = i >> 5;
        const int c4  = i & 31;
        float4 v4 = reinterpret_cast<const float4*>(Qg)[i];
        __half h0, h1, h2, h3, l0, l1, l2, l3;
        split2h(v4.x * qscale, h0, l0);
        split2h(v4.y * qscale, h1, l1);
        split2h(v4.z * qscale, h2, l2);
        split2h(v4.w * qscale, h3, l3);
        __half2* d1 = reinterpret_cast<__half2*>(sq1 + row * QS + c4 * 4);
        __half2* d2 = reinterpret_cast<__half2*>(sq2 + row * QS + c4 * 4);
        d1[0] = __halves2half2(h0, h1);
        d1[1] = __halves2half2(h2, h3);
        d2[0] = __halves2half2(l0, l1);
        d2[1] = __halves2half2(l2, l3);
    }

    float m_lo = -1e30f, m_hi = -1e30f;
    float l_lo = 0.0f,   l_hi = 0.0f;
    float o[16][4];
    #pragma unroll
    for (int i = 0; i < 16; i++) { o[i][0]=0.f; o[i][1]=0.f; o[i][2]=0.f; o[i][3]=0.f; }

    // ---- ldmatrix lane bases (relative to buffer 0; add bofs per iter) ----
    const uint32_t a_row = (uint32_t)(wr + (lane & 7) + ((lane >> 3) & 1) * 8);
    const uint32_t a_c8  = (uint32_t)((lane >> 4) * 8);
    const uint32_t sq1_ld = sbase + (a_row * QS + a_c8) * 2u;
    const uint32_t sq2_ld = sq1_ld + (uint32_t)SQ2_E * 2u;
    const uint32_t b_row = (uint32_t)((lane & 7) + ((lane >> 4) << 3));
    const uint32_t b_c8  = (uint32_t)(((lane >> 3) & 1) * 8);
    const uint32_t sk1_ld = buf_sa0 + (b_row * KS + b_c8) * 2u;
    const uint32_t sk2_ld = sk1_ld + (uint32_t)N_SK * 2u;
    const int mi = lane >> 3, mj = lane & 7;
    const uint32_t sv_lane_elem = (uint32_t)(((mi & 1) * 8 + mj) * KS + (mi >> 1) * 8);
    const uint32_t sv1_base = buf_sa0 + 2u * N_SK * 2u + sv_lane_elem * 2u;
    const uint32_t sp_ld = sbase + (uint32_t)SP_E * 2u + (a_row * PS + a_c8) * 2u;

    for (int kt = 0; kt < NT; kt++) {
        // ---- wait for tile kt (keep <=1 in flight) ----
        if (kt + 1 < NT) asm volatile("cp.async.wait_group 1;\n" ::: "memory");
        else             asm volatile("cp.async.wait_group 0;\n" ::: "memory");
        __syncthreads();
        const uint32_t bofs = (uint32_t)(kt & 1) * (uint32_t)(BUF_ELEMS * 2);

        // ---- S = Q K^T: q1k1 + q2k1 + q1k2, fragments via ldmatrix ----
        float s[8][4];
        #pragma unroll
        for (int nt = 0; nt < 8; nt++) {
            s[nt][0]=0.f; s[nt][1]=0.f; s[nt][2]=0.f; s[nt][3]=0.f;
        }
        #pragma unroll
        for (int kc = 0; kc < 8; kc++) {
            uint32_t a1[4], a2[4];
            ldsm_x4(a1[0], a1[1], a1[2], a1[3], sq1_ld + kc * 32u);
            ldsm_x4(a2[0], a2[1], a2[2], a2[3], sq2_ld + kc * 32u);
            #pragma unroll
            for (int pr = 0; pr < 4; pr++) {
                const uint32_t boff = (uint32_t)(pr * 16 * KS + kc * 16) * 2u + bofs;
                uint32_t b1[4], b2[4];
                ldsm_x4(b1[0], b1[1], b1[2], b1[3], sk1_ld + boff);
                ldsm_x4(b2[0], b2[1], b2[2], b2[3], sk2_ld + boff);
                mma_f16(s[2*pr],   a1[0],a1[1],a1[2],a1[3], b1[0], b1[1]);
                mma_f16(s[2*pr+1], a1[0],a1[1],a1[2],a1[3], b1[2], b1[3]);
                mma_f16(s[2*pr],   a2[0],a2[1],a2[2],a2[3], b1[0], b1[1]);
                mma_f16(s[2*pr+1], a2[0],a2[1],a2[2],a2[3], b1[2], b1[3]);
                mma_f16(s[2*pr],   a1[0],a1[1],a1[2],a1[3], b2[0], b2[1]);
                mma_f16(s[2*pr+1], a1[0],a1[1],a1[2],a1[3], b2[2], b2[3]);
            }
        }

        // ---- online softmax (base-2) ----
        float mx_lo = -1e30f, mx_hi = -1e30f;
        #pragma unroll
        for (int nt = 0; nt < 8; nt++) {
            mx_lo = fmaxf(mx_lo, fmaxf(s[nt][0], s[nt][1]));
            mx_hi = fmaxf(mx_hi, fmaxf(s[nt][2], s[nt][3]));
        }
        mx_lo = fmaxf(mx_lo, __shfl_xor_sync(0xffffffffu, mx_lo, 1));
        mx_lo = fmaxf(mx_lo, __shfl_xor_sync(0xffffffffu, mx_lo, 2));
        mx_hi = fmaxf(mx_hi, __shfl_xor_sync(0xffffffffu, mx_hi, 1));
        mx_hi = fmaxf(mx_hi, __shfl_xor_sync(0xffffffffu, mx_hi, 2));

        const float mnew_lo = fmaxf(m_lo, mx_lo);
        const float mnew_hi = fmaxf(m_hi, mx_hi);
        const float corr_lo = ex2f(m_lo - mnew_lo);
        const float corr_hi = ex2f(m_hi - mnew_hi);
        m_lo = mnew_lo;
        m_hi = mnew_hi;

        float sum_lo = 0.f, sum_hi = 0.f;
        #pragma unroll
        for (int nt = 0; nt < 8; nt++) {
            const __half h0 = __float2half_rn(ex2f(s[nt][0] - m_lo));
            const __half h1 = __float2half_rn(ex2f(s[nt][1] - m_lo));
            const __half h2 = __float2half_rn(ex2f(s[nt][2] - m_hi));
            const __half h3 = __float2half_rn(ex2f(s[nt][3] - m_hi));
            sum_lo += __half2float(h0) + __half2float(h1);
            sum_hi += __half2float(h2) + __half2float(h3);
            *reinterpret_cast<__half2*>(sp + (wr + g)     * PS + nt * 8 + 2 * t) =
                __halves2half2(h0, h1);
            *reinterpret_cast<__half2*>(sp + (wr + g + 8) * PS + nt * 8 + 2 * t) =
                __halves2half2(h2, h3);
        }
        sum_lo += __shfl_xor_sync(0xffffffffu, sum_lo, 1);
        sum_lo += __shfl_xor_sync(0xffffffffu, sum_lo, 2);
        sum_hi += __shfl_xor_sync(0xffffffffu, sum_hi, 1);
        sum_hi += __shfl_xor_sync(0xffffffffu, sum_hi, 2);

        l_lo = l_lo * corr_lo + sum_lo;
        l_hi = l_hi * corr_hi + sum_hi;

        #pragma unroll
        for (int nt = 0; nt < 16; nt++) {
            o[nt][0] *= corr_lo; o[nt][1] *= corr_lo;
            o[nt][2] *= corr_hi; o[nt][3] *= corr_hi;
        }
        __syncwarp();   // sp rows are warp-private

        // ---- O += P~ V~ (single pass) ----
        #pragma unroll
        for (int kc = 0; kc < 4; kc++) {
            uint32_t p[4];
            ldsm_x4(p[0], p[1], p[2], p[3], sp_ld + kc * 32u);
            #pragma unroll
            for (int ntp = 0; ntp < 8; ntp++) {
                const uint32_t off = (uint32_t)(kc * 16 * KS + ntp * 16) * 2u + bofs;
                uint32_t v0, v1, v2, v3;
                ldsm_x4_t(v0, v1, v2, v3, sv1_base + off);
                mma_f16(o[2*ntp],   p[0], p[1], p[2], p[3], v0, v1);
                mma_f16(o[2*ntp+1], p[0], p[1], p[2], p[3], v2, v3);
            }
        }

        // ---- refill the buffer we just finished with tile kt+2 ----
        if (kt + 2 < NT) {
            __syncthreads();   // all warps done reading buf[kt&1]
            const size_t e = (size_t)(kt + 2) * BN * DH;
            issue_kv(tid, (kt & 1) ? buf_sa1 : buf_sa0, Kh0 + e, Kl0 + e, Vh0 + e);
        }
    }

    // ---- normalize and write out ----
    const float inv_lo = 1.0f / l_lo;
    const float inv_hi = 1.0f / l_hi;
    #pragma unroll
    for (int nt = 0; nt < 16; nt++) {
        const int c = nt * 8 + 2 * t;
        *reinterpret_cast<float2*>(Og + (wr + g)     * DH + c) =
            make_float2(o[nt][0] * inv_lo, o[nt][1] * inv_lo);
        *reinterpret_cast<float2*>(Og + (wr + g + 8) * DH + c) =
            make_float2(o[nt][2] * inv_hi, o[nt][3] * inv_hi);
    }
}

extern "C" void kernel_launch(void* const* d_in, const int* in_sizes, int n_in,
                              void* d_out, int out_size) {
    const float* q = (const float*)d_in[0];
    const float* k = (const float*)d_in[1];
    const float* v = (const float*)d_in[2];
    float* out = (float*)d_out;

    cudaFuncSetAttribute(attn_fwd_kernel,
                         cudaFuncAttributeMaxDynamicSharedMemorySize, SMEM_BYTES);

    split_kv_kernel<<<(int)(KVELEMS / 4 / 256), 256>>>(k, v);
    dim3 grid(SEQ / BM, 64);
    attn_fwd_kernel<<<grid, NTHREADS, SMEM_BYTES>>>(q, out);
}